// round 15
// baseline (speedup 1.0000x reference)
#include <cuda_runtime.h>

#define HW (1024 * 1024)
#define NB 16
#define BLOCKS_PER_BATCH 64
#define NBLOCKS (NB * BLOCKS_PER_BATCH)   // 1024
#define THREADS 256
#define EPS 1e-6f

// per-batch running sums: {S_p, S_pp, S_tp, S_t}, accumulated via atomicAdd
__device__ float4 g_sums[NB];             // zero-initialized at load; reset by last block
__device__ unsigned int g_count = 0;      // self-resetting

__device__ __forceinline__ void accum(float l0, float l1, int t,
                                      float& sp, float& spp, float& stp, float& st) {
    // p1 = sigmoid(l1 - l0) = 1 / (1 + exp(l0 - l1))
    float e = __expf(l0 - l1);
    float p = __fdividef(1.0f, 1.0f + e);
    float tf = __int2float_rn(t);         // t in {0,1}
    sp  += p;
    spp += p * p;
    stp += tf * p;
    st  += tf;
}

__global__ __launch_bounds__(THREADS, 8)
void dice_fused_kernel(const float* __restrict__ logits,
                       const int* __restrict__ labels,
                       float* __restrict__ out) {
    // batch-major CTA ordering (measured best: clustered launch-front locality)
    const int b   = blockIdx.x / BLOCKS_PER_BATCH;
    const int blk = blockIdx.x % BLOCKS_PER_BATCH;

    const float4* __restrict__ l0v = (const float4*)(logits + (size_t)b * 2 * HW);
    const float4* __restrict__ l1v = (const float4*)(logits + (size_t)b * 2 * HW + HW);
    const int4*   __restrict__ tv  = (const int4*)(labels + (size_t)b * HW);

    const int n4        = HW / 4;                  // 262144 float4 per plane
    const int per_block = n4 / BLOCKS_PER_BATCH;   // 4096
    const int base      = blk * per_block;

    float sp = 0.f, spp = 0.f, stp = 0.f, st = 0.f;

#pragma unroll 4
    for (int i = threadIdx.x; i < per_block; i += THREADS) {
        float4 a = l0v[base + i];
        float4 c = l1v[base + i];
        int4   t = tv[base + i];
        accum(a.x, c.x, t.x, sp, spp, stp, st);
        accum(a.y, c.y, t.y, sp, spp, stp, st);
        accum(a.z, c.z, t.z, sp, spp, stp, st);
        accum(a.w, c.w, t.w, sp, spp, stp, st);
    }

    // block reduce to one float4
#pragma unroll
    for (int o = 16; o > 0; o >>= 1) {
        sp  += __shfl_down_sync(0xFFFFFFFFu, sp, o);
        spp += __shfl_down_sync(0xFFFFFFFFu, spp, o);
        stp += __shfl_down_sync(0xFFFFFFFFu, stp, o);
        st  += __shfl_down_sync(0xFFFFFFFFu, st, o);
    }

    __shared__ float4 sh[THREADS / 32];
    __shared__ bool   amLast;
    const int wid  = threadIdx.x >> 5;
    const int lane = threadIdx.x & 31;
    if (lane == 0) sh[wid] = make_float4(sp, spp, stp, st);
    __syncthreads();

    if (wid == 0) {
        float4 v = (lane < THREADS / 32) ? sh[lane] : make_float4(0.f, 0.f, 0.f, 0.f);
#pragma unroll
        for (int o = 4; o > 0; o >>= 1) {
            v.x += __shfl_down_sync(0xFFFFFFFFu, v.x, o);
            v.y += __shfl_down_sync(0xFFFFFFFFu, v.y, o);
            v.z += __shfl_down_sync(0xFFFFFFFFu, v.z, o);
            v.w += __shfl_down_sync(0xFFFFFFFFu, v.w, o);
        }
        if (lane == 0) {
            float* dst = (float*)&g_sums[b];
            atomicAdd(dst + 0, v.x);
            atomicAdd(dst + 1, v.y);
            atomicAdd(dst + 2, v.z);
            atomicAdd(dst + 3, v.w);
            __threadfence();
            unsigned int prev = atomicAdd(&g_count, 1u);
            amLast = (prev == NBLOCKS - 1);
        }
    }
    __syncthreads();

    // ---- last block: tiny finish (one warp) ----
    if (amLast && wid == 0) {
        float dice = 0.f;
        if (lane < NB) {
            volatile float* vp = (volatile float*)&g_sums[lane];
            float vx = vp[0];
            float vy = vp[1];
            float vz = vp[2];
            float vw = vp[3];
            const float N = (float)HW;
            // channel 1
            float num1 = 2.0f * vz;
            float den1 = vy + vw;                 // S_pp + S_t (t^2 = t)
            // channel 0 (p0 = 1-p1, t0 = 1-t1)
            float num0 = 2.0f * (N - vw - vx + vz);
            float den0 = (N - 2.0f * vx + vy) + (N - vw);
            dice = num1 / (den1 + EPS) + num0 / (den0 + EPS);
        }
#pragma unroll
        for (int o = 16; o > 0; o >>= 1)
            dice += __shfl_down_sync(0xFFFFFFFFu, dice, o);
        if (lane == 0) {
            out[0] = 1.0f - dice / (float)(2 * NB);
        }
        // deterministic reset for next (graph-replayed) launch
        if (lane < NB) {
            g_sums[lane] = make_float4(0.f, 0.f, 0.f, 0.f);
        }
        if (lane == 0) g_count = 0;
    }
}

extern "C" void kernel_launch(void* const* d_in, const int* in_sizes, int n_in,
                              void* d_out, int out_size) {
    const float* logits = (const float*)d_in[0];
    const int*   labels = (const int*)d_in[1];
    float*       out    = (float*)d_out;

    dice_fused_kernel<<<NBLOCKS, THREADS>>>(logits, labels, out);
}

// round 16
// speedup vs baseline: 1.0567x; 1.0567x over previous
#include <cuda_runtime.h>

#define HW (1024 * 1024)
#define NB 16
#define BLOCKS_PER_BATCH 32
#define NBLOCKS (NB * BLOCKS_PER_BATCH)   // 512
#define THREADS 512
#define EPS 1e-6f

// per-batch running sums: {S_p, S_pp, S_tp, S_t}, accumulated via atomicAdd
__device__ float4 g_sums[NB];             // zero-initialized at load; reset by last block
__device__ unsigned int g_count = 0;      // self-resetting

__device__ __forceinline__ void accum(float l0, float l1, int t,
                                      float& sp, float& spp, float& stp, float& st) {
    // p1 = sigmoid(l1 - l0) = 1 / (1 + exp(l0 - l1))
    float e = __expf(l0 - l1);
    float p = __fdividef(1.0f, 1.0f + e);
    float tf = __int2float_rn(t);         // t in {0,1}
    sp  += p;
    spp += p * p;
    stp += tf * p;
    st  += tf;
}

__global__ __launch_bounds__(THREADS, 4)
void dice_fused_kernel(const float* __restrict__ logits,
                       const int* __restrict__ labels,
                       float* __restrict__ out) {
    // batch-major CTA ordering (measured best: clustered launch-front locality)
    const int b   = blockIdx.x / BLOCKS_PER_BATCH;
    const int blk = blockIdx.x % BLOCKS_PER_BATCH;

    const float4* __restrict__ l0v = (const float4*)(logits + (size_t)b * 2 * HW);
    const float4* __restrict__ l1v = (const float4*)(logits + (size_t)b * 2 * HW + HW);
    const int4*   __restrict__ tv  = (const int4*)(labels + (size_t)b * HW);

    const int n4        = HW / 4;                  // 262144 float4 per plane
    const int per_block = n4 / BLOCKS_PER_BATCH;   // 8192
    const int base      = blk * per_block;

    float sp = 0.f, spp = 0.f, stp = 0.f, st = 0.f;

#pragma unroll 4
    for (int i = threadIdx.x; i < per_block; i += THREADS) {
        float4 a = l0v[base + i];
        float4 c = l1v[base + i];
        int4   t = tv[base + i];
        accum(a.x, c.x, t.x, sp, spp, stp, st);
        accum(a.y, c.y, t.y, sp, spp, stp, st);
        accum(a.z, c.z, t.z, sp, spp, stp, st);
        accum(a.w, c.w, t.w, sp, spp, stp, st);
    }

    // block reduce to one float4
#pragma unroll
    for (int o = 16; o > 0; o >>= 1) {
        sp  += __shfl_down_sync(0xFFFFFFFFu, sp, o);
        spp += __shfl_down_sync(0xFFFFFFFFu, spp, o);
        stp += __shfl_down_sync(0xFFFFFFFFu, stp, o);
        st  += __shfl_down_sync(0xFFFFFFFFu, st, o);
    }

    __shared__ float4 sh[THREADS / 32];
    __shared__ bool   amLast;
    const int wid  = threadIdx.x >> 5;
    const int lane = threadIdx.x & 31;
    if (lane == 0) sh[wid] = make_float4(sp, spp, stp, st);
    __syncthreads();

    if (wid == 0) {
        float4 v = (lane < THREADS / 32) ? sh[lane] : make_float4(0.f, 0.f, 0.f, 0.f);
#pragma unroll
        for (int o = 8; o > 0; o >>= 1) {
            v.x += __shfl_down_sync(0xFFFFFFFFu, v.x, o);
            v.y += __shfl_down_sync(0xFFFFFFFFu, v.y, o);
            v.z += __shfl_down_sync(0xFFFFFFFFu, v.z, o);
            v.w += __shfl_down_sync(0xFFFFFFFFu, v.w, o);
        }
        if (lane == 0) {
            float* dst = (float*)&g_sums[b];
            atomicAdd(dst + 0, v.x);
            atomicAdd(dst + 1, v.y);
            atomicAdd(dst + 2, v.z);
            atomicAdd(dst + 3, v.w);
            __threadfence();
            unsigned int prev = atomicAdd(&g_count, 1u);
            amLast = (prev == NBLOCKS - 1);
        }
    }
    __syncthreads();

    // ---- last block: tiny finish (one warp) ----
    if (amLast && wid == 0) {
        float dice = 0.f;
        if (lane < NB) {
            volatile float* vp = (volatile float*)&g_sums[lane];
            float vx = vp[0];
            float vy = vp[1];
            float vz = vp[2];
            float vw = vp[3];
            const float N = (float)HW;
            // channel 1
            float num1 = 2.0f * vz;
            float den1 = vy + vw;                 // S_pp + S_t (t^2 = t)
            // channel 0 (p0 = 1-p1, t0 = 1-t1)
            float num0 = 2.0f * (N - vw - vx + vz);
            float den0 = (N - 2.0f * vx + vy) + (N - vw);
            dice = num1 / (den1 + EPS) + num0 / (den0 + EPS);
        }
#pragma unroll
        for (int o = 16; o > 0; o >>= 1)
            dice += __shfl_down_sync(0xFFFFFFFFu, dice, o);
        if (lane == 0) {
            out[0] = 1.0f - dice / (float)(2 * NB);
        }
        // deterministic reset for next (graph-replayed) launch
        if (lane < NB) {
            g_sums[lane] = make_float4(0.f, 0.f, 0.f, 0.f);
        }
        if (lane == 0) g_count = 0;
    }
}

extern "C" void kernel_launch(void* const* d_in, const int* in_sizes, int n_in,
                              void* d_out, int out_size) {
    const float* logits = (const float*)d_in[0];
    const int*   labels = (const int*)d_in[1];
    float*       out    = (float*)d_out;

    dice_fused_kernel<<<NBLOCKS, THREADS>>>(logits, labels, out);
}